// round 11
// baseline (speedup 1.0000x reference)
#include <cuda_runtime.h>
#include <cuda_bf16.h>
#include <cstdint>

#define B_  512
#define T_  1024
#define IN_ 128
#define NG_ 256
#define BT_ (B_ * T_)
#define MTILES 4096          // BT_/128 m-tiles per dir

// xg scratch: [dir][b*T+t][hh*4 + slot], slot: 0=i,1=g,2=f,3=o  (1 GiB)
__device__ float g_G[(size_t)2 * BT_ * NG_];

// ---------------- smem map (bytes) for gates_gemm ----------------
// bf16 tiles, row stride 136 elems = 272 B (conflict-free ldmatrix)
#define XSTRIDE 272
#define SM_XHI  0
#define SM_XLO  (SM_XHI + 128 * XSTRIDE)     //  34816
#define SM_WHI  (SM_XLO + 128 * XSTRIDE)     //  69632
#define SM_WLO  (SM_WHI + 256 * XSTRIDE)     // 139264
#define SM_BIAS (SM_WLO + 256 * XSTRIDE)     // 208896
#define SM_TOTAL (SM_BIAS + 1024)            // 209920

// ---------------- ptx helpers ----------------
__device__ __forceinline__ uint32_t smem_u32(const void* p) {
    return (uint32_t)__cvta_generic_to_shared(p);
}
__device__ __forceinline__ void ldsm4(uint32_t* r, uint32_t addr) {
    asm volatile("ldmatrix.sync.aligned.m8n8.x4.shared.b16 {%0,%1,%2,%3}, [%4];"
                 : "=r"(r[0]), "=r"(r[1]), "=r"(r[2]), "=r"(r[3]) : "r"(addr));
}
__device__ __forceinline__ void mma16816(float* c, const uint32_t* a,
                                         uint32_t b0, uint32_t b1) {
    asm volatile(
        "mma.sync.aligned.m16n8k16.row.col.f32.bf16.bf16.f32 "
        "{%0,%1,%2,%3}, {%4,%5,%6,%7}, {%8,%9}, {%0,%1,%2,%3};"
        : "+f"(c[0]), "+f"(c[1]), "+f"(c[2]), "+f"(c[3])
        : "r"(a[0]), "r"(a[1]), "r"(a[2]), "r"(a[3]), "r"(b0), "r"(b1));
}

// bf16x2 pack: low half = lo arg, high half = hi arg
__device__ __forceinline__ uint32_t pack_bf16x2(float lo, float hi) {
    uint32_t r;
    asm("cvt.rn.bf16x2.f32 %0, %1, %2;" : "=r"(r) : "f"(hi), "f"(lo));
    return r;
}
// hi/lo split of two floats -> packed bf16x2 hi + residual bf16x2 lo
__device__ __forceinline__ void split2(float a, float b, uint32_t& hi, uint32_t& lo) {
    hi = pack_bf16x2(a, b);
    float ra = a - __uint_as_float(hi << 16);
    float rb = b - __uint_as_float(hi & 0xFFFF0000u);
    lo = pack_bf16x2(ra, rb);
}

// ---------------- activations (MUFU tanh) ----------------
__device__ __forceinline__ float tanh_fast(float x) {
    float y;
    asm("tanh.approx.f32 %0, %1;" : "=f"(y) : "f"(x));
    return y;
}

// ---------------- f32x2 / cp.async (recurrence) ----------------
__device__ __forceinline__ unsigned long long ffma2(unsigned long long a,
                                                    unsigned long long b,
                                                    unsigned long long c) {
    unsigned long long d;
    asm("fma.rn.f32x2 %0, %1, %2, %3;" : "=l"(d) : "l"(a), "l"(b), "l"(c));
    return d;
}
__device__ __forceinline__ float red2(unsigned long long v) {
    unsigned int a, b;
    asm("mov.b64 {%0, %1}, %2;" : "=r"(a), "=r"(b) : "l"(v));
    return __uint_as_float(a) + __uint_as_float(b);
}
__device__ __forceinline__ void cp_async4(uint32_t dst, const void* src) {
    asm volatile("cp.async.ca.shared.global [%0], [%1], 4;" :: "r"(dst), "l"(src));
}
__device__ __forceinline__ void cp_commit() {
    asm volatile("cp.async.commit_group;");
}
__device__ __forceinline__ void cp_wait1() {
    asm volatile("cp.async.wait_group 1;");
}

// =======================================================================
// Kernel 1: HMMA split-precision GEMM (exact R9 winner, 595us).
// D[128m,256p] = xhi*Whi + xhi*Wlo + xlo*Whi  (fp32 register accs).
// 148 CTAs x 512 thr (16 warps): warp tile 32m x 64n.
// =======================================================================
__global__ void __launch_bounds__(512, 1) gates_gemm(
    const float* __restrict__ x,
    const float* __restrict__ Wf, const float* __restrict__ bf,
    const float* __restrict__ Wb, const float* __restrict__ bb)
{
    extern __shared__ char sm[];
    const uint32_t smb = smem_u32(sm);

    const int tid  = threadIdx.x;
    const int wid  = tid >> 5;
    const int lane = tid & 31;
    const int dir  = blockIdx.x & 1;
    const int cpos = blockIdx.x >> 1;   // 0..73

    const float* W    = dir ? Wb : Wf;
    const float* bias = dir ? bb : bf;

    // ---- load + split W at permuted row p (once) ----
    {
        const int j    = tid >> 1;          // 0..255
        const int half = tid & 1;           // k half: cols 0-63 / 64-127
        const int g    = j >> 6;
        const int slot = (g == 0) ? 0 : (g == 1) ? 2 : (g == 2) ? 1 : 3;
        const int p    = ((j & 63) << 2) | slot;
        const float4* wr = (const float4*)(W + j * IN_ + half * 64);
        char* whi = sm + SM_WHI + p * XSTRIDE + half * 128;
        char* wlo = sm + SM_WLO + p * XSTRIDE + half * 128;
#pragma unroll
        for (int q = 0; q < 16; q++) {
            float4 v = wr[q];
            uint32_t h0, l0, h1, l1;
            split2(v.x, v.y, h0, l0);
            split2(v.z, v.w, h1, l1);
            *(uint2*)(whi + q * 8) = make_uint2(h0, h1);
            *(uint2*)(wlo + q * 8) = make_uint2(l0, l1);
        }
        if (half == 0) ((float*)(sm + SM_BIAS))[p] = bias[j];
    }

    // warp tiling
    const int msub  = (wid & 3) * 32;
    const int nsub0 = (wid >> 2) * 64;

    // ldmatrix lane address components
    const uint32_t aoff = (uint32_t)(msub + (lane & 15)) * XSTRIDE + (lane >> 4) * 16;
    const uint32_t boff = (uint32_t)(nsub0 + (lane & 7) + ((lane >> 4) << 3)) * XSTRIDE
                          + ((lane >> 3) & 1) * 16;

    const int r0c = tid >> 5;     // conversion row base
    const int lc  = tid & 31;     // conversion col4

    for (int mt = cpos; mt < MTILES; mt += 74) {
        __syncthreads();   // x smem free (first iter: also orders W split)

        // ---- load + split x tile ----
        {
            const float* srcb = x + (size_t)mt * 128 * IN_;
#pragma unroll
            for (int i = 0; i < 4; i++) {
                const int row0 = r0c + 32 * i;
                float4 v0 = *(const float4*)(srcb + (size_t)row0 * IN_ + lc * 4);
                float4 v1 = *(const float4*)(srcb + (size_t)(row0 + 16) * IN_ + lc * 4);
                uint32_t h0, l0, h1, l1;
                split2(v0.x, v0.y, h0, l0);
                split2(v0.z, v0.w, h1, l1);
                *(uint2*)(sm + SM_XHI + row0 * XSTRIDE + lc * 8) = make_uint2(h0, h1);
                *(uint2*)(sm + SM_XLO + row0 * XSTRIDE + lc * 8) = make_uint2(l0, l1);
                split2(v1.x, v1.y, h0, l0);
                split2(v1.z, v1.w, h1, l1);
                *(uint2*)(sm + SM_XHI + (row0 + 16) * XSTRIDE + lc * 8) = make_uint2(h0, h1);
                *(uint2*)(sm + SM_XLO + (row0 + 16) * XSTRIDE + lc * 8) = make_uint2(l0, l1);
            }
        }
        __syncthreads();

        // ---- fused 3-term mma accumulate ----
        float acc[2][8][4];
#pragma unroll
        for (int m2 = 0; m2 < 2; m2++)
#pragma unroll
            for (int j = 0; j < 8; j++)
#pragma unroll
                for (int q = 0; q < 4; q++) acc[m2][j][q] = 0.f;

        const uint32_t aHi = smb + SM_XHI + aoff;
        const uint32_t aLo = smb + SM_XLO + aoff;
        const uint32_t bHi = smb + SM_WHI + boff;
        const uint32_t bLo = smb + SM_WLO + boff;

#pragma unroll
        for (int k8 = 0; k8 < 8; k8++) {
            uint32_t ah0[4], ah1[4], al0[4], al1[4];
            ldsm4(ah0, aHi + k8 * 32);
            ldsm4(ah1, aHi + 16 * XSTRIDE + k8 * 32);
            ldsm4(al0, aLo + k8 * 32);
            ldsm4(al1, aLo + 16 * XSTRIDE + k8 * 32);
#pragma unroll
            for (int jp = 0; jp < 4; jp++) {
                uint32_t bh[4], bl[4];
                ldsm4(bh, bHi + jp * (16 * XSTRIDE) + k8 * 32);
                ldsm4(bl, bLo + jp * (16 * XSTRIDE) + k8 * 32);
                mma16816(acc[0][2 * jp + 0], ah0, bh[0], bh[1]);
                mma16816(acc[0][2 * jp + 1], ah0, bh[2], bh[3]);
                mma16816(acc[1][2 * jp + 0], ah1, bh[0], bh[1]);
                mma16816(acc[1][2 * jp + 1], ah1, bh[2], bh[3]);
                mma16816(acc[0][2 * jp + 0], ah0, bl[0], bl[1]);
                mma16816(acc[0][2 * jp + 1], ah0, bl[2], bl[3]);
                mma16816(acc[1][2 * jp + 0], ah1, bl[0], bl[1]);
                mma16816(acc[1][2 * jp + 1], ah1, bl[2], bl[3]);
                mma16816(acc[0][2 * jp + 0], al0, bh[0], bh[1]);
                mma16816(acc[0][2 * jp + 1], al0, bh[2], bh[3]);
                mma16816(acc[1][2 * jp + 0], al1, bh[0], bh[1]);
                mma16816(acc[1][2 * jp + 1], al1, bh[2], bh[3]);
            }
        }

        // ---- epilogue: bias + store to g_G ----
        {
            const int g  = lane >> 2;
            const int t2 = (lane & 3) * 2;
            const float* bsm = (const float*)(sm + SM_BIAS);
#pragma unroll
            for (int m2 = 0; m2 < 2; m2++) {
                const size_t mrow = (size_t)mt * 128 + msub + m2 * 16 + g;
                float* r0 = g_G + ((size_t)dir * BT_ + mrow) * NG_;
                float* r1 = r0 + 8 * NG_;
#pragma unroll
                for (int j = 0; j < 8; j++) {
                    const int col = nsub0 + 8 * j + t2;
                    float2 bv = *(const float2*)(bsm + col);
                    *(float2*)(r0 + col) =
                        make_float2(acc[m2][j][0] + bv.x, acc[m2][j][1] + bv.y);
                    *(float2*)(r1 + col) =
                        make_float2(acc[m2][j][2] + bv.x, acc[m2][j][3] + bv.y);
                }
            }
        }
    }
}

// =======================================================================
// Kernel 2: recurrence, 256 thr/CTA, 1 gate-row/thread.
// 256 CTAs = (2 dirs) x (128 chunks of 4 batches), 2 CTAs/SM ->
// 16 warps/SM (4/SMSP), ~110 regs/thread (no spill).
// Thread = (hh = tid>>2, slot = tid&3), slot: 0=i,1=g,2=f,3=o;
// j row = slot-dependent. Whh row k-pair packed in regs (64 regs).
// Gate exchange: shfl.xor 1 (i<->g, f<->o) then shfl.xor 2 (->f lane).
// c,h live on slot2 (f) lanes. xg cp.async one step ahead; 1 bar/step.
// =======================================================================
__global__ void __launch_bounds__(256, 2) lstm_rec(
    const float* __restrict__ Whh_f, const float* __restrict__ Whh_b,
    float* __restrict__ out)
{
    __shared__ __align__(16) float h_s[2][4][64];
    __shared__ __align__(16) float xg_s[2][4][256];

    const int tid  = threadIdx.x;
    const int dir  = blockIdx.x >> 7;
    const int b0   = (blockIdx.x & 127) << 2;
    const int slot = tid & 3;
    const int hh   = tid >> 2;

    const float* Whh = dir ? Whh_b : Whh_f;

    // j row: i->hh, g->128+hh, f->64+hh, o->192+hh
    const int j = ((slot & 1) << 7) + ((slot >> 1) << 6) + hh;

    unsigned long long w2[32];
    {
        const ulonglong2* rw = (const ulonglong2*)(Whh + j * 64);
#pragma unroll
        for (int i = 0; i < 16; i++) {
            ulonglong2 v = rw[i];
            w2[2 * i] = v.x;
            w2[2 * i + 1] = v.y;
        }
    }

    // act: slot1 (g) -> tanh(x); others -> sigmoid(x) = 0.5*tanh(0.5x)+0.5
    const float s1 = (slot == 1) ? 1.0f : 0.5f;
    const float m1 = (slot == 1) ? 1.0f : 0.5f;
    const float c1 = (slot == 1) ? 0.0f : 0.5f;

    // init h buffers (512 floats)
    ((float*)h_s)[tid] = 0.f;
    ((float*)h_s)[tid + 256] = 0.f;
    float c[4] = {0.f, 0.f, 0.f, 0.f};

    // xg source: g_G[dir][ (b0+b)*T + t ][tid]
    const float* xg_src = g_G + (size_t)dir * BT_ * NG_ + tid;
    const uint32_t xgs_u32 = (uint32_t)__cvta_generic_to_shared(&xg_s[0][0][0]);
    float* outb = out + dir * 64 + hh;

    // prologue: prefetch step 0 into buf 0
    {
        const int t0 = dir ? (T_ - 1) : 0;
#pragma unroll
        for (int b = 0; b < 4; b++)
            cp_async4(xgs_u32 + (b * 256 + tid) * 4,
                      xg_src + ((size_t)(b0 + b) * T_ + t0) * NG_);
        cp_commit();
    }
    __syncthreads();

    for (int s = 0; s < T_; s++) {
        const int t = dir ? (T_ - 1 - s) : s;

        // prefetch xg for step s+1 into the other buffer
        if (s + 1 < T_) {
            const int tn = dir ? (T_ - 2 - s) : (s + 1);
            const uint32_t dst = xgs_u32 + ((s + 1) & 1) * 4096;
#pragma unroll
            for (int b = 0; b < 4; b++)
                cp_async4(dst + (b * 256 + tid) * 4,
                          xg_src + ((size_t)(b0 + b) * T_ + tn) * NG_);
        }
        cp_commit();

        const float* cur = &h_s[s & 1][0][0];
        float* nxt = &h_s[(s & 1) ^ 1][0][0];

        // matvec: a[b] = sum_k h[b][k] * w[k]  (k-pair packed)
        unsigned long long a[4] = {0, 0, 0, 0};
#pragma unroll
        for (int q = 0; q < 16; q++) {
#pragma unroll
            for (int b = 0; b < 4; b++) {
                ulonglong2 hb = *(const ulonglong2*)(cur + b * 64 + 4 * q);
                a[b] = ffma2(hb.x, w2[2 * q], a[b]);
                a[b] = ffma2(hb.y, w2[2 * q + 1], a[b]);
            }
        }

        cp_wait1();   // step s's xg complete (s+1's may pend)

#pragma unroll
        for (int b = 0; b < 4; b++) {
            const float g0 = red2(a[b]) + xg_s[s & 1][b][tid];
            // own gate activation
            const float t0 = fmaf(tanh_fast(g0 * s1), m1, c1);
            // xor1: i<->g, f<->o
            const float e1 = __shfl_xor_sync(0xFFFFFFFFu, t0, 1);
            // on i lanes: p = sig(i)*tanh(g); on f lanes: e1 = sig(o)
            const float pv = t0 * e1;
            // xor2: i<->f, g<->o : f lane receives p from i lane
            const float p = __shfl_xor_sync(0xFFFFFFFFu, pv, 2);
            // f lane: c = sig(f)*c + sig(i)*tanh(g)
            c[b] = fmaf(t0, c[b], p);
            const float h = e1 * tanh_fast(c[b]);   // sig(o)*tanh(c)

            if (slot == 2) {
                nxt[b * 64 + hh] = h;
                outb[((size_t)(b0 + b) * T_ + t) * 128] = h;
            }
        }
        __syncthreads();
    }
}

// =======================================================================
extern "C" void kernel_launch(void* const* d_in, const int* in_sizes, int n_in,
                              void* d_out, int out_size)
{
    const float* x    = (const float*)d_in[0];
    const float* Wihf = (const float*)d_in[1];
    const float* Whhf = (const float*)d_in[2];
    const float* bf   = (const float*)d_in[3];
    const float* Wihb = (const float*)d_in[4];
    const float* Whhb = (const float*)d_in[5];
    const float* bb   = (const float*)d_in[6];
    float* out = (float*)d_out;

    cudaFuncSetAttribute(gates_gemm, cudaFuncAttributeMaxDynamicSharedMemorySize, SM_TOTAL);

    gates_gemm<<<148, 512, SM_TOTAL>>>(x, Wihf, bf, Wihb, bb);
    lstm_rec<<<256, 256>>>(Whhf, Whhb, out);
}

// round 12
// speedup vs baseline: 1.3122x; 1.3122x over previous
#include <cuda_runtime.h>
#include <cuda_fp16.h>
#include <cstdint>

#define B_  512
#define T_  1024
#define IN_ 128
#define NG_ 256
#define BT_ (B_ * T_)
#define MTILES 4096          // BT_/128 m-tiles per dir

// xg scratch: [dir][b*T+t][hh*4 + slot], slot: 0=i,1=g,2=f,3=o  (1 GiB)
__device__ float g_G[(size_t)2 * BT_ * NG_];

// ---------------- smem map (bytes) for gates_gemm ----------------
// f16 tiles, row stride 136 elems = 272 B (conflict-free ldmatrix)
#define XSTRIDE 272
#define SM_XH   0
#define SM_WHI  (SM_XH + 128 * XSTRIDE)      //  34816
#define SM_WLO  (SM_WHI + 256 * XSTRIDE)     // 104448
#define SM_BIAS (SM_WLO + 256 * XSTRIDE)     // 174080
#define SM_TOTAL (SM_BIAS + 1024)            // 175104

// ---------------- ptx helpers ----------------
__device__ __forceinline__ uint32_t smem_u32(const void* p) {
    return (uint32_t)__cvta_generic_to_shared(p);
}
__device__ __forceinline__ void ldsm4(uint32_t* r, uint32_t addr) {
    asm volatile("ldmatrix.sync.aligned.m8n8.x4.shared.b16 {%0,%1,%2,%3}, [%4];"
                 : "=r"(r[0]), "=r"(r[1]), "=r"(r[2]), "=r"(r[3]) : "r"(addr));
}
__device__ __forceinline__ void mma16816(float* c, const uint32_t* a,
                                         uint32_t b0, uint32_t b1) {
    asm volatile(
        "mma.sync.aligned.m16n8k16.row.col.f32.f16.f16.f32 "
        "{%0,%1,%2,%3}, {%4,%5,%6,%7}, {%8,%9}, {%0,%1,%2,%3};"
        : "+f"(c[0]), "+f"(c[1]), "+f"(c[2]), "+f"(c[3])
        : "r"(a[0]), "r"(a[1]), "r"(a[2]), "r"(a[3]), "r"(b0), "r"(b1));
}

// fp16x2 pack of two floats (lo half = a, hi half = b)
__device__ __forceinline__ uint32_t cvt2h(float a, float b) {
    __half2 h = __floats2half2_rn(a, b);
    return *reinterpret_cast<uint32_t*>(&h);
}
// fp16 hi/lo split of two floats: hi = rn(x), lo = rn(x - hi)
__device__ __forceinline__ void split2h(float a, float b, uint32_t& hi, uint32_t& lo) {
    __half2 h = __floats2half2_rn(a, b);
    hi = *reinterpret_cast<uint32_t*>(&h);
    __half2 r = __floats2half2_rn(a - __half2float(__low2half(h)),
                                  b - __half2float(__high2half(h)));
    lo = *reinterpret_cast<uint32_t*>(&r);
}

// ---------------- activations (MUFU tanh) ----------------
__device__ __forceinline__ float tanh_fast(float x) {
    float y;
    asm("tanh.approx.f32 %0, %1;" : "=f"(y) : "f"(x));
    return y;
}
__device__ __forceinline__ float sig_fast(float x) {
    return fmaf(tanh_fast(0.5f * x), 0.5f, 0.5f);
}

// ---------------- f32x2 / cp.async (recurrence) ----------------
__device__ __forceinline__ unsigned long long ffma2(unsigned long long a,
                                                    unsigned long long b,
                                                    unsigned long long c) {
    unsigned long long d;
    asm("fma.rn.f32x2 %0, %1, %2, %3;" : "=l"(d) : "l"(a), "l"(b), "l"(c));
    return d;
}
__device__ __forceinline__ float red2(unsigned long long v) {
    unsigned int a, b;
    asm("mov.b64 {%0, %1}, %2;" : "=r"(a), "=r"(b) : "l"(v));
    return __uint_as_float(a) + __uint_as_float(b);
}
__device__ __forceinline__ void cp_async8(uint32_t dst, const void* src) {
    asm volatile("cp.async.ca.shared.global [%0], [%1], 8;" :: "r"(dst), "l"(src));
}
__device__ __forceinline__ void cp_commit() {
    asm volatile("cp.async.commit_group;");
}
__device__ __forceinline__ void cp_wait1() {
    asm volatile("cp.async.wait_group 1;");
}

// =======================================================================
// Kernel 1: HMMA fp16 2-term split GEMM.
// D[128m,256p] = x16*Whi + x16*Wlo  (fp32 register accs), where
// x16 = f16(x) (e5m10, rel err ~5e-4) and W = Whi + Wlo (f16 pair,
// rep err ~3e-8). 256 mma/tile/warp vs 384 for the bf16 3-term.
// 148 CTAs x 512 thr (16 warps): warp tile 32m x 64n. R9 structure.
// =======================================================================
__global__ void __launch_bounds__(512, 1) gates_gemm(
    const float* __restrict__ x,
    const float* __restrict__ Wf, const float* __restrict__ bf,
    const float* __restrict__ Wb, const float* __restrict__ bb)
{
    extern __shared__ char sm[];
    const uint32_t smb = smem_u32(sm);

    const int tid  = threadIdx.x;
    const int wid  = tid >> 5;
    const int lane = tid & 31;
    const int dir  = blockIdx.x & 1;
    const int cpos = blockIdx.x >> 1;   // 0..73

    const float* W    = dir ? Wb : Wf;
    const float* bias = dir ? bb : bf;

    // ---- load + split W at permuted row p (once) ----
    {
        const int j    = tid >> 1;          // 0..255
        const int half = tid & 1;           // k half: cols 0-63 / 64-127
        const int g    = j >> 6;
        const int slot = (g == 0) ? 0 : (g == 1) ? 2 : (g == 2) ? 1 : 3;
        const int p    = ((j & 63) << 2) | slot;
        const float4* wr = (const float4*)(W + j * IN_ + half * 64);
        char* whi = sm + SM_WHI + p * XSTRIDE + half * 128;
        char* wlo = sm + SM_WLO + p * XSTRIDE + half * 128;
#pragma unroll
        for (int q = 0; q < 16; q++) {
            float4 v = wr[q];
            uint32_t h0, l0, h1, l1;
            split2h(v.x, v.y, h0, l0);
            split2h(v.z, v.w, h1, l1);
            *(uint2*)(whi + q * 8) = make_uint2(h0, h1);
            *(uint2*)(wlo + q * 8) = make_uint2(l0, l1);
        }
        if (half == 0) ((float*)(sm + SM_BIAS))[p] = bias[j];
    }

    // warp tiling
    const int msub  = (wid & 3) * 32;
    const int nsub0 = (wid >> 2) * 64;

    // ldmatrix lane address components
    const uint32_t aoff = (uint32_t)(msub + (lane & 15)) * XSTRIDE + (lane >> 4) * 16;
    const uint32_t boff = (uint32_t)(nsub0 + (lane & 7) + ((lane >> 4) << 3)) * XSTRIDE
                          + ((lane >> 3) & 1) * 16;

    const int r0c = tid >> 5;     // conversion row base
    const int lc  = tid & 31;     // conversion col4

    for (int mt = cpos; mt < MTILES; mt += 74) {
        __syncthreads();   // x smem free (first iter: also orders W split)

        // ---- load + convert x tile to f16 ----
        {
            const float* srcb = x + (size_t)mt * 128 * IN_;
#pragma unroll
            for (int i = 0; i < 4; i++) {
                const int row0 = r0c + 32 * i;
                float4 v0 = *(const float4*)(srcb + (size_t)row0 * IN_ + lc * 4);
                float4 v1 = *(const float4*)(srcb + (size_t)(row0 + 16) * IN_ + lc * 4);
                *(uint2*)(sm + SM_XH + row0 * XSTRIDE + lc * 8) =
                    make_uint2(cvt2h(v0.x, v0.y), cvt2h(v0.z, v0.w));
                *(uint2*)(sm + SM_XH + (row0 + 16) * XSTRIDE + lc * 8) =
                    make_uint2(cvt2h(v1.x, v1.y), cvt2h(v1.z, v1.w));
            }
        }
        __syncthreads();

        // ---- fused 2-term mma accumulate ----
        float acc[2][8][4];
#pragma unroll
        for (int m2 = 0; m2 < 2; m2++)
#pragma unroll
            for (int j = 0; j < 8; j++)
#pragma unroll
                for (int q = 0; q < 4; q++) acc[m2][j][q] = 0.f;

        const uint32_t aH  = smb + SM_XH + aoff;
        const uint32_t bHi = smb + SM_WHI + boff;
        const uint32_t bLo = smb + SM_WLO + boff;

#pragma unroll
        for (int k8 = 0; k8 < 8; k8++) {
            uint32_t ah0[4], ah1[4];
            ldsm4(ah0, aH + k8 * 32);
            ldsm4(ah1, aH + 16 * XSTRIDE + k8 * 32);
#pragma unroll
            for (int jp = 0; jp < 4; jp++) {
                uint32_t bh[4], bl[4];
                ldsm4(bh, bHi + jp * (16 * XSTRIDE) + k8 * 32);
                ldsm4(bl, bLo + jp * (16 * XSTRIDE) + k8 * 32);
                mma16816(acc[0][2 * jp + 0], ah0, bh[0], bh[1]);
                mma16816(acc[0][2 * jp + 1], ah0, bh[2], bh[3]);
                mma16816(acc[1][2 * jp + 0], ah1, bh[0], bh[1]);
                mma16816(acc[1][2 * jp + 1], ah1, bh[2], bh[3]);
                mma16816(acc[0][2 * jp + 0], ah0, bl[0], bl[1]);
                mma16816(acc[0][2 * jp + 1], ah0, bl[2], bl[3]);
                mma16816(acc[1][2 * jp + 0], ah1, bl[0], bl[1]);
                mma16816(acc[1][2 * jp + 1], ah1, bl[2], bl[3]);
            }
        }

        // ---- epilogue: bias + store to g_G ----
        {
            const int g  = lane >> 2;
            const int t2 = (lane & 3) * 2;
            const float* bsm = (const float*)(sm + SM_BIAS);
#pragma unroll
            for (int m2 = 0; m2 < 2; m2++) {
                const size_t mrow = (size_t)mt * 128 + msub + m2 * 16 + g;
                float* r0 = g_G + ((size_t)dir * BT_ + mrow) * NG_;
                float* r1 = r0 + 8 * NG_;
#pragma unroll
                for (int j = 0; j < 8; j++) {
                    const int col = nsub0 + 8 * j + t2;
                    float2 bv = *(const float2*)(bsm + col);
                    *(float2*)(r0 + col) =
                        make_float2(acc[m2][j][0] + bv.x, acc[m2][j][1] + bv.y);
                    *(float2*)(r1 + col) =
                        make_float2(acc[m2][j][2] + bv.x, acc[m2][j][3] + bv.y);
                }
            }
        }
    }
}

// =======================================================================
// Kernel 2: recurrence — R6 winner, byte-for-byte (no de-phasing).
// 256 CTAs = (2 dirs) x (128 chunks of 4 batches), 128 thr, 2 CTAs/SM.
// Thread = (hh = tid>>1, type = tid&1): 2 gate rows each, weights in
// regs, xg cp.async one step ahead, 1 shfl gate exchange, 1 bar/step.
// =======================================================================
__global__ void __launch_bounds__(128, 2) lstm_rec(
    const float* __restrict__ Whh_f, const float* __restrict__ Whh_b,
    float* __restrict__ out)
{
    __shared__ __align__(16) float h_s[2][4][64];
    __shared__ __align__(16) float2 xg_s[2][4][128];

    const int tid  = threadIdx.x;
    const int dir  = blockIdx.x >> 7;
    const int b0   = (blockIdx.x & 127) << 2;
    const int hh   = tid >> 1;
    const int type = tid & 1;

    const float* Whh = dir ? Whh_b : Whh_f;

    const int j0 = type ? (64 + hh) : hh;
    const int j1 = j0 + 128;

    unsigned long long w2a[32], w2b[32];
    {
        const ulonglong2* ra = (const ulonglong2*)(Whh + j0 * 64);
        const ulonglong2* rb = (const ulonglong2*)(Whh + j1 * 64);
#pragma unroll
        for (int i = 0; i < 16; i++) {
            ulonglong2 va = ra[i], vb = rb[i];
            w2a[2 * i] = va.x; w2a[2 * i + 1] = va.y;
            w2b[2 * i] = vb.x; w2b[2 * i + 1] = vb.y;
        }
    }

    const float s1 = type ? 0.5f : 1.0f;
    const float m1 = type ? 0.5f : 1.0f;
    const float c1 = type ? 0.5f : 0.0f;

#pragma unroll
    for (int i = 0; i < 4; i++) ((float*)h_s)[tid + i * 128] = 0.f;
    float c[4] = {0.f, 0.f, 0.f, 0.f};

    const float* xg_src = g_G + ((size_t)dir * BT_) * NG_ + (size_t)hh * 4 + type * 2;
    const uint32_t xgs_u32 = (uint32_t)__cvta_generic_to_shared(&xg_s[0][0][0]);
    float* outb = out + dir * 64 + hh;

    {
        const int t0 = dir ? (T_ - 1) : 0;
#pragma unroll
        for (int b = 0; b < 4; b++)
            cp_async8(xgs_u32 + (b * 128 + tid) * 8,
                      xg_src + ((size_t)(b0 + b) * T_ + t0) * NG_);
        cp_commit();
    }
    __syncthreads();

    for (int s = 0; s < T_; s++) {
        const int t = dir ? (T_ - 1 - s) : s;

        if (s + 1 < T_) {
            const int tn = dir ? (T_ - 2 - s) : (s + 1);
            const uint32_t dst = xgs_u32 + ((s + 1) & 1) * 4096;
#pragma unroll
            for (int b = 0; b < 4; b++)
                cp_async8(dst + (b * 128 + tid) * 8,
                          xg_src + ((size_t)(b0 + b) * T_ + tn) * NG_);
        }
        cp_commit();

        const float* cur = &h_s[s & 1][0][0];
        float* nxt = &h_s[(s & 1) ^ 1][0][0];

        unsigned long long a0[4] = {0, 0, 0, 0}, a1[4] = {0, 0, 0, 0};
#pragma unroll
        for (int q = 0; q < 16; q++) {
#pragma unroll
            for (int b = 0; b < 4; b++) {
                ulonglong2 hb = *(const ulonglong2*)(cur + b * 64 + 4 * q);
                a0[b] = ffma2(hb.x, w2a[2 * q], a0[b]);
                a0[b] = ffma2(hb.y, w2a[2 * q + 1], a0[b]);
                a1[b] = ffma2(hb.x, w2b[2 * q], a1[b]);
                a1[b] = ffma2(hb.y, w2b[2 * q + 1], a1[b]);
            }
        }

        cp_wait1();

#pragma unroll
        for (int b = 0; b < 4; b++) {
            const float2 xg = xg_s[s & 1][b][tid];
            const float g0 = red2(a0[b]) + xg.x;
            const float g1 = red2(a1[b]) + xg.y;

            const float t0  = sig_fast(g0);
            const float t1v = fmaf(tanh_fast(g1 * s1), m1, c1);

            const float v  = t0 * t1v;
            const float vr = __shfl_xor_sync(0xFFFFFFFFu, v, 1);

            c[b] = fmaf(t0, c[b], vr);
            const float h = t1v * tanh_fast(c[b]);

            if (type) {
                nxt[b * 64 + hh] = h;
                outb[((size_t)(b0 + b) * T_ + t) * 128] = h;
            }
        }
        __syncthreads();
    }
}

// =======================================================================
extern "C" void kernel_launch(void* const* d_in, const int* in_sizes, int n_in,
                              void* d_out, int out_size)
{
    const float* x    = (const float*)d_in[0];
    const float* Wihf = (const float*)d_in[1];
    const float* Whhf = (const float*)d_in[2];
    const float* bf   = (const float*)d_in[3];
    const float* Wihb = (const float*)d_in[4];
    const float* Whhb = (const float*)d_in[5];
    const float* bb   = (const float*)d_in[6];
    float* out = (float*)d_out;

    cudaFuncSetAttribute(gates_gemm, cudaFuncAttributeMaxDynamicSharedMemorySize, SM_TOTAL);

    gates_gemm<<<148, 512, SM_TOTAL>>>(x, Wihf, bf, Wihb, bb);
    lstm_rec<<<256, 128>>>(Whhf, Whhb, out);
}

// round 13
// speedup vs baseline: 1.4370x; 1.0952x over previous
#include <cuda_runtime.h>
#include <cuda_fp16.h>
#include <cstdint>

#define B_  512
#define T_  1024
#define IN_ 128
#define NG_ 256
#define BT_ (B_ * T_)
#define MTILES 4096          // BT_/128 m-tiles per dir

// xg scratch: [dir][b*T+t][hh*4 + slot], slot: 0=i,1=g,2=f,3=o  (1 GiB)
__device__ float g_G[(size_t)2 * BT_ * NG_];

// ---------------- smem map (bytes) for gates_gemm ----------------
// f16 tiles, row stride 136 elems = 272 B (conflict-free ldmatrix)
#define XSTRIDE 272
#define SM_XH   0
#define SM_WHI  (SM_XH + 128 * XSTRIDE)      //  34816
#define SM_BIAS (SM_WHI + 256 * XSTRIDE)     // 104448
#define SM_TOTAL (SM_BIAS + 1024)            // 105472

// ---------------- ptx helpers ----------------
__device__ __forceinline__ uint32_t smem_u32(const void* p) {
    return (uint32_t)__cvta_generic_to_shared(p);
}
__device__ __forceinline__ void ldsm4(uint32_t* r, uint32_t addr) {
    asm volatile("ldmatrix.sync.aligned.m8n8.x4.shared.b16 {%0,%1,%2,%3}, [%4];"
                 : "=r"(r[0]), "=r"(r[1]), "=r"(r[2]), "=r"(r[3]) : "r"(addr));
}
__device__ __forceinline__ void mma16816(float* c, const uint32_t* a,
                                         uint32_t b0, uint32_t b1) {
    asm volatile(
        "mma.sync.aligned.m16n8k16.row.col.f32.f16.f16.f32 "
        "{%0,%1,%2,%3}, {%4,%5,%6,%7}, {%8,%9}, {%0,%1,%2,%3};"
        : "+f"(c[0]), "+f"(c[1]), "+f"(c[2]), "+f"(c[3])
        : "r"(a[0]), "r"(a[1]), "r"(a[2]), "r"(a[3]), "r"(b0), "r"(b1));
}

// fp16x2 pack of two floats (lo half = a, hi half = b)
__device__ __forceinline__ uint32_t cvt2h(float a, float b) {
    __half2 h = __floats2half2_rn(a, b);
    return *reinterpret_cast<uint32_t*>(&h);
}

// ---------------- activations (MUFU tanh) ----------------
__device__ __forceinline__ float tanh_fast(float x) {
    float y;
    asm("tanh.approx.f32 %0, %1;" : "=f"(y) : "f"(x));
    return y;
}
__device__ __forceinline__ float sig_fast(float x) {
    return fmaf(tanh_fast(0.5f * x), 0.5f, 0.5f);
}

// ---------------- f32x2 / cp.async (recurrence) ----------------
__device__ __forceinline__ unsigned long long ffma2(unsigned long long a,
                                                    unsigned long long b,
                                                    unsigned long long c) {
    unsigned long long d;
    asm("fma.rn.f32x2 %0, %1, %2, %3;" : "=l"(d) : "l"(a), "l"(b), "l"(c));
    return d;
}
__device__ __forceinline__ float red2(unsigned long long v) {
    unsigned int a, b;
    asm("mov.b64 {%0, %1}, %2;" : "=r"(a), "=r"(b) : "l"(v));
    return __uint_as_float(a) + __uint_as_float(b);
}
__device__ __forceinline__ void cp_async8(uint32_t dst, const void* src) {
    asm volatile("cp.async.ca.shared.global [%0], [%1], 8;" :: "r"(dst), "l"(src));
}
__device__ __forceinline__ void cp_commit() {
    asm volatile("cp.async.commit_group;");
}
__device__ __forceinline__ void cp_wait1() {
    asm volatile("cp.async.wait_group 1;");
}

// =======================================================================
// Kernel 1: HMMA pure-fp16 GEMM (1 term).
// D[128m,256p] = f16(x) @ f16(W)^T  (fp32 register accs).
// Error model: x err 4.9e-4 (+) W err 4.9e-4 -> output ~4e-4 (<1e-3).
// 128 mma + 48 ldsm per tile/warp (half of the R12 2-term version).
// 148 CTAs x 512 thr (16 warps): warp tile 32m x 64n.
// =======================================================================
__global__ void __launch_bounds__(512, 1) gates_gemm(
    const float* __restrict__ x,
    const float* __restrict__ Wf, const float* __restrict__ bf,
    const float* __restrict__ Wb, const float* __restrict__ bb)
{
    extern __shared__ char sm[];
    const uint32_t smb = smem_u32(sm);

    const int tid  = threadIdx.x;
    const int wid  = tid >> 5;
    const int lane = tid & 31;
    const int dir  = blockIdx.x & 1;
    const int cpos = blockIdx.x >> 1;   // 0..73

    const float* W    = dir ? Wb : Wf;
    const float* bias = dir ? bb : bf;

    // ---- load + convert W to f16 at permuted row p (once) ----
    {
        const int j    = tid >> 1;          // 0..255
        const int half = tid & 1;           // k half: cols 0-63 / 64-127
        const int g    = j >> 6;
        const int slot = (g == 0) ? 0 : (g == 1) ? 2 : (g == 2) ? 1 : 3;
        const int p    = ((j & 63) << 2) | slot;
        const float4* wr = (const float4*)(W + j * IN_ + half * 64);
        char* whi = sm + SM_WHI + p * XSTRIDE + half * 128;
#pragma unroll
        for (int q = 0; q < 16; q++) {
            float4 v = wr[q];
            *(uint2*)(whi + q * 8) = make_uint2(cvt2h(v.x, v.y), cvt2h(v.z, v.w));
        }
        if (half == 0) ((float*)(sm + SM_BIAS))[p] = bias[j];
    }

    // warp tiling
    const int msub  = (wid & 3) * 32;
    const int nsub0 = (wid >> 2) * 64;

    // ldmatrix lane address components
    const uint32_t aoff = (uint32_t)(msub + (lane & 15)) * XSTRIDE + (lane >> 4) * 16;
    const uint32_t boff = (uint32_t)(nsub0 + (lane & 7) + ((lane >> 4) << 3)) * XSTRIDE
                          + ((lane >> 3) & 1) * 16;

    const int r0c = tid >> 5;     // conversion row base
    const int lc  = tid & 31;     // conversion col4

    for (int mt = cpos; mt < MTILES; mt += 74) {
        __syncthreads();   // x smem free (first iter: also orders W convert)

        // ---- load + convert x tile to f16 ----
        {
            const float* srcb = x + (size_t)mt * 128 * IN_;
#pragma unroll
            for (int i = 0; i < 4; i++) {
                const int row0 = r0c + 32 * i;
                float4 v0 = *(const float4*)(srcb + (size_t)row0 * IN_ + lc * 4);
                float4 v1 = *(const float4*)(srcb + (size_t)(row0 + 16) * IN_ + lc * 4);
                *(uint2*)(sm + SM_XH + row0 * XSTRIDE + lc * 8) =
                    make_uint2(cvt2h(v0.x, v0.y), cvt2h(v0.z, v0.w));
                *(uint2*)(sm + SM_XH + (row0 + 16) * XSTRIDE + lc * 8) =
                    make_uint2(cvt2h(v1.x, v1.y), cvt2h(v1.z, v1.w));
            }
        }
        __syncthreads();

        // ---- 1-term mma accumulate ----
        float acc[2][8][4];
#pragma unroll
        for (int m2 = 0; m2 < 2; m2++)
#pragma unroll
            for (int j = 0; j < 8; j++)
#pragma unroll
                for (int q = 0; q < 4; q++) acc[m2][j][q] = 0.f;

        const uint32_t aH  = smb + SM_XH + aoff;
        const uint32_t bHi = smb + SM_WHI + boff;

#pragma unroll
        for (int k8 = 0; k8 < 8; k8++) {
            uint32_t ah0[4], ah1[4];
            ldsm4(ah0, aH + k8 * 32);
            ldsm4(ah1, aH + 16 * XSTRIDE + k8 * 32);
#pragma unroll
            for (int jp = 0; jp < 4; jp++) {
                uint32_t bh[4];
                ldsm4(bh, bHi + jp * (16 * XSTRIDE) + k8 * 32);
                mma16816(acc[0][2 * jp + 0], ah0, bh[0], bh[1]);
                mma16816(acc[0][2 * jp + 1], ah0, bh[2], bh[3]);
                mma16816(acc[1][2 * jp + 0], ah1, bh[0], bh[1]);
                mma16816(acc[1][2 * jp + 1], ah1, bh[2], bh[3]);
            }
        }

        // ---- epilogue: bias + store to g_G ----
        {
            const int g  = lane >> 2;
            const int t2 = (lane & 3) * 2;
            const float* bsm = (const float*)(sm + SM_BIAS);
#pragma unroll
            for (int m2 = 0; m2 < 2; m2++) {
                const size_t mrow = (size_t)mt * 128 + msub + m2 * 16 + g;
                float* r0 = g_G + ((size_t)dir * BT_ + mrow) * NG_;
                float* r1 = r0 + 8 * NG_;
#pragma unroll
                for (int j = 0; j < 8; j++) {
                    const int col = nsub0 + 8 * j + t2;
                    float2 bv = *(const float2*)(bsm + col);
                    *(float2*)(r0 + col) =
                        make_float2(acc[m2][j][0] + bv.x, acc[m2][j][1] + bv.y);
                    *(float2*)(r1 + col) =
                        make_float2(acc[m2][j][2] + bv.x, acc[m2][j][3] + bv.y);
                }
            }
        }
    }
}

// =======================================================================
// Kernel 2: recurrence — R6 winner, byte-for-byte (frozen at its floor).
// 256 CTAs = (2 dirs) x (128 chunks of 4 batches), 128 thr, 2 CTAs/SM.
// Thread = (hh = tid>>1, type = tid&1): 2 gate rows each, weights in
// regs, xg cp.async one step ahead, 1 shfl gate exchange, 1 bar/step.
// =======================================================================
__global__ void __launch_bounds__(128, 2) lstm_rec(
    const float* __restrict__ Whh_f, const float* __restrict__ Whh_b,
    float* __restrict__ out)
{
    __shared__ __align__(16) float h_s[2][4][64];
    __shared__ __align__(16) float2 xg_s[2][4][128];

    const int tid  = threadIdx.x;
    const int dir  = blockIdx.x >> 7;
    const int b0   = (blockIdx.x & 127) << 2;
    const int hh   = tid >> 1;
    const int type = tid & 1;

    const float* Whh = dir ? Whh_b : Whh_f;

    const int j0 = type ? (64 + hh) : hh;
    const int j1 = j0 + 128;

    unsigned long long w2a[32], w2b[32];
    {
        const ulonglong2* ra = (const ulonglong2*)(Whh + j0 * 64);
        const ulonglong2* rb = (const ulonglong2*)(Whh + j1 * 64);
#pragma unroll
        for (int i = 0; i < 16; i++) {
            ulonglong2 va = ra[i], vb = rb[i];
            w2a[2 * i] = va.x; w2a[2 * i + 1] = va.y;
            w2b[2 * i] = vb.x; w2b[2 * i + 1] = vb.y;
        }
    }

    const float s1 = type ? 0.5f : 1.0f;
    const float m1 = type ? 0.5f : 1.0f;
    const float c1 = type ? 0.5f : 0.0f;

#pragma unroll
    for (int i = 0; i < 4; i++) ((float*)h_s)[tid + i * 128] = 0.f;
    float c[4] = {0.f, 0.f, 0.f, 0.f};

    const float* xg_src = g_G + ((size_t)dir * BT_) * NG_ + (size_t)hh * 4 + type * 2;
    const uint32_t xgs_u32 = (uint32_t)__cvta_generic_to_shared(&xg_s[0][0][0]);
    float* outb = out + dir * 64 + hh;

    {
        const int t0 = dir ? (T_ - 1) : 0;
#pragma unroll
        for (int b = 0; b < 4; b++)
            cp_async8(xgs_u32 + (b * 128 + tid) * 8,
                      xg_src + ((size_t)(b0 + b) * T_ + t0) * NG_);
        cp_commit();
    }
    __syncthreads();

    for (int s = 0; s < T_; s++) {
        const int t = dir ? (T_ - 1 - s) : s;

        if (s + 1 < T_) {
            const int tn = dir ? (T_ - 2 - s) : (s + 1);
            const uint32_t dst = xgs_u32 + ((s + 1) & 1) * 4096;
#pragma unroll
            for (int b = 0; b < 4; b++)
                cp_async8(dst + (b * 128 + tid) * 8,
                          xg_src + ((size_t)(b0 + b) * T_ + tn) * NG_);
        }
        cp_commit();

        const float* cur = &h_s[s & 1][0][0];
        float* nxt = &h_s[(s & 1) ^ 1][0][0];

        unsigned long long a0[4] = {0, 0, 0, 0}, a1[4] = {0, 0, 0, 0};
#pragma unroll
        for (int q = 0; q < 16; q++) {
#pragma unroll
            for (int b = 0; b < 4; b++) {
                ulonglong2 hb = *(const ulonglong2*)(cur + b * 64 + 4 * q);
                a0[b] = ffma2(hb.x, w2a[2 * q], a0[b]);
                a0[b] = ffma2(hb.y, w2a[2 * q + 1], a0[b]);
                a1[b] = ffma2(hb.x, w2b[2 * q], a1[b]);
                a1[b] = ffma2(hb.y, w2b[2 * q + 1], a1[b]);
            }
        }

        cp_wait1();

#pragma unroll
        for (int b = 0; b < 4; b++) {
            const float2 xg = xg_s[s & 1][b][tid];
            const float g0 = red2(a0[b]) + xg.x;
            const float g1 = red2(a1[b]) + xg.y;

            const float t0  = sig_fast(g0);
            const float t1v = fmaf(tanh_fast(g1 * s1), m1, c1);

            const float v  = t0 * t1v;
            const float vr = __shfl_xor_sync(0xFFFFFFFFu, v, 1);

            c[b] = fmaf(t0, c[b], vr);
            const float h = t1v * tanh_fast(c[b]);

            if (type) {
                nxt[b * 64 + hh] = h;
                outb[((size_t)(b0 + b) * T_ + t) * 128] = h;
            }
        }
        __syncthreads();
    }
}

// =======================================================================
extern "C" void kernel_launch(void* const* d_in, const int* in_sizes, int n_in,
                              void* d_out, int out_size)
{
    const float* x    = (const float*)d_in[0];
    const float* Wihf = (const float*)d_in[1];
    const float* Whhf = (const float*)d_in[2];
    const float* bf   = (const float*)d_in[3];
    const float* Wihb = (const float*)d_in[4];
    const float* Whhb = (const float*)d_in[5];
    const float* bb   = (const float*)d_in[6];
    float* out = (float*)d_out;

    cudaFuncSetAttribute(gates_gemm, cudaFuncAttributeMaxDynamicSharedMemorySize, SM_TOTAL);

    gates_gemm<<<148, 512, SM_TOTAL>>>(x, Wihf, bf, Wihb, bb);
    lstm_rec<<<256, 128>>>(Whhf, Whhb, out);
}